// round 6
// baseline (speedup 1.0000x reference)
#include <cuda_runtime.h>
#include <cuda_fp16.h>
#include <math.h>
#include <stdint.h>
#include <float.h>

#define N_RULES 50000
#define N_PAD   50176            // 196 * 256
#define NHALF   25088            // rules per CTA-half
#define TILES   98               // NHALF / 256
#define D_DIM   384
#define B_ROWS  8192
#define H_DIM   256
#define TOPK    8
#define TOPK_C  16               // coarse candidates per half
#define NCAND   32               // 2 halves * 16

#define BM 128
#define BN 256
#define BK 64
#define KCH 6                    // 384 / 64
#define TOT (TILES * KCH)        // 588
#define ASTRIDE 392              // halves: 384 + 8 (784B row -> conflict-free LDSM)
#define BSTRIDE 72               // halves: 64 + 8  (144B row)
#define NTHREADS 512

// ---------------- device scratch ----------------
__device__ __half g_rh[(size_t)N_PAD * D_DIM];
__device__ float  g_rinv[N_PAD];
__device__ __half g_qh[(size_t)B_ROWS * D_DIM];
__device__ float  g_qinv[B_ROWS];
__device__ int    g_topi[(size_t)B_ROWS * NCAND];
__device__ float  g_w8f[(size_t)B_ROWS * TOPK];
__device__ int    g_i8f[(size_t)B_ROWS * TOPK];

// ---------------- smem struct ----------------
struct __align__(16) SimsSmem {
    __half As[BM * ASTRIDE];            // 100352 B
    __half Bs[3][BN * BSTRIDE];         // 110592 B
    float topv[BM * TOPK_C];            // 8192 B
    int   topi[BM * TOPK_C];            // 8192 B
    float thr[BM];
    int   lck[BM];
};                                      // ~228.3 KB total

// ---------------- PTX helpers ----------------
__device__ __forceinline__ uint32_t smem_u32(const void* p) {
    uint32_t a;
    asm("{ .reg .u64 t; cvta.to.shared.u64 t, %1; cvt.u32.u64 %0, t; }" : "=r"(a) : "l"(p));
    return a;
}
__device__ __forceinline__ void cp16(uint32_t dst, const void* src) {
    asm volatile("cp.async.cg.shared.global [%0], [%1], 16;" :: "r"(dst), "l"(src));
}
__device__ __forceinline__ void ldsm_x4(uint32_t* r, uint32_t addr) {
    asm volatile("ldmatrix.sync.aligned.m8n8.x4.shared.b16 {%0,%1,%2,%3}, [%4];"
                 : "=r"(r[0]), "=r"(r[1]), "=r"(r[2]), "=r"(r[3]) : "r"(addr));
}
// f16 accumulator MMA: c packs 2x f16 per reg, 2 regs
__device__ __forceinline__ void mma16816_f16(uint32_t* c, const uint32_t* a,
                                             uint32_t b0, uint32_t b1) {
    asm volatile(
        "mma.sync.aligned.m16n8k16.row.col.f16.f16.f16.f16 "
        "{%0,%1}, {%2,%3,%4,%5}, {%6,%7}, {%0,%1};\n"
        : "+r"(c[0]), "+r"(c[1])
        : "r"(a[0]), "r"(a[1]), "r"(a[2]), "r"(a[3]), "r"(b0), "r"(b1));
}

// ---------------- prep kernels: normalize + f16 quantize -------------------
__global__ void prep_rules_kernel(const float* __restrict__ src) {
    int row = blockIdx.x;
    int tid = threadIdx.x;  // 128
    if (row >= N_RULES) {
        for (int d = tid; d < D_DIM; d += 128)
            g_rh[(size_t)row * D_DIM + d] = __float2half(0.0f);
        if (tid == 0) g_rinv[row] = 0.0f;
        return;
    }
    const float* x = src + (size_t)row * D_DIM;
    float s = 0.0f;
    for (int d = tid; d < D_DIM; d += 128) { float v = x[d]; s += v * v; }
    __shared__ float red[4];
    for (int o = 16; o; o >>= 1) s += __shfl_xor_sync(0xffffffffu, s, o);
    if ((tid & 31) == 0) red[tid >> 5] = s;
    __syncthreads();
    if (tid == 0) {
        float t = red[0] + red[1] + red[2] + red[3];
        red[0] = 1.0f / fmaxf(sqrtf(t), 1e-12f);
    }
    __syncthreads();
    float inv = red[0];
    for (int d = tid; d < D_DIM; d += 128)
        g_rh[(size_t)row * D_DIM + d] = __float2half(x[d] * inv);
    if (tid == 0) g_rinv[row] = inv;
}

__global__ void prep_q_kernel(const float* __restrict__ src) {
    int row = blockIdx.x;
    int tid = threadIdx.x;  // 128
    const float* x = src + (size_t)row * D_DIM;
    float s = 0.0f;
    for (int d = tid; d < D_DIM; d += 128) { float v = x[d]; s += v * v; }
    __shared__ float red[4];
    for (int o = 16; o; o >>= 1) s += __shfl_xor_sync(0xffffffffu, s, o);
    if ((tid & 31) == 0) red[tid >> 5] = s;
    __syncthreads();
    if (tid == 0) {
        float t = red[0] + red[1] + red[2] + red[3];
        red[0] = 1.0f / fmaxf(sqrtf(t), 1e-12f);
    }
    __syncthreads();
    float inv = red[0];
    for (int d = tid; d < D_DIM; d += 128)
        g_qh[(size_t)row * D_DIM + d] = __float2half(x[d] * inv);
    if (tid == 0) g_qinv[row] = inv;
}

// ---------------- fused f16 sims GEMM + streaming coarse top-16 ------------
__device__ __forceinline__ void issue_b_chunk(uint32_t sbB, int tid, int ch, int rule0) {
    int t  = ch / KCH;
    int kc = ch - t * KCH;
    const __half* src = g_rh + ((size_t)rule0 + (size_t)t * BN) * D_DIM + kc * BK;
    uint32_t bbase = sbB + (uint32_t)(ch % 3) * (BN * BSTRIDE * 2);
    #pragma unroll
    for (int i = 0; i < 4; ++i) {   // 256 rows * 8 uint4 = 2048 / 512 thr
        int e = tid + i * NTHREADS;
        int r = e >> 3;
        int u = e & 7;
        cp16(bbase + (uint32_t)(r * BSTRIDE + u * 8) * 2, src + (size_t)r * D_DIM + u * 8);
    }
    asm volatile("cp.async.commit_group;" ::: "memory");
}

__device__ void topk_insert(SimsSmem* sm, int r, float v, int j) {
    bool done = false;
    while (!done) {
        if (atomicCAS(&sm->lck[r], 0, 1) == 0) {
            volatile float* tv = sm->topv + r * TOPK_C;
            volatile int*   ti = sm->topi + r * TOPK_C;
            float mn = tv[0]; int mp = 0;
            #pragma unroll
            for (int p = 1; p < TOPK_C; ++p) { float x = tv[p]; if (x < mn) { mn = x; mp = p; } }
            if (v > mn) {
                tv[mp] = v;
                ti[mp] = j;
                float nm = v;
                #pragma unroll
                for (int p = 0; p < TOPK_C; ++p) { float x = tv[p]; if (x < nm) nm = x; }
                sm->thr[r] = nm;
            }
            __threadfence_block();
            atomicExch(&sm->lck[r], 0);
            done = true;
        }
    }
}

__global__ __launch_bounds__(NTHREADS, 1)
void sims_topk_kernel() {
    extern __shared__ char smraw[];
    SimsSmem* sm = reinterpret_cast<SimsSmem*>(smraw);
    const uint32_t sbA = smem_u32(sm->As);
    const uint32_t sbB = smem_u32(sm->Bs);

    const int tid    = threadIdx.x;
    const int lane   = tid & 31;
    const int wid    = tid >> 5;            // 0..15
    const int wm     = (wid & 3) * 32;      // 4 m-warps over 128 rows
    const int wn     = (wid >> 2) * 64;     // 4 n-warps over 256 cols
    const int grp    = blockIdx.x >> 1;
    const int half   = blockIdx.x & 1;
    const int row0   = grp * BM;
    const int rule0  = half * NHALF;

    for (int i = tid; i < BM * TOPK_C; i += NTHREADS) { sm->topv[i] = -FLT_MAX; sm->topi[i] = 0; }
    for (int i = tid; i < BM; i += NTHREADS)          { sm->thr[i]  = -FLT_MAX; sm->lck[i]  = 0; }

    // resident A: 128 rows x 384 f16
    {
        const uint4* gq = reinterpret_cast<const uint4*>(g_qh + (size_t)row0 * D_DIM);
        for (int i = tid; i < BM * 48; i += NTHREADS) {
            int r = i / 48, u = i - (i / 48) * 48;
            *reinterpret_cast<uint4*>(
                reinterpret_cast<char*>(sm->As) + (size_t)r * (ASTRIDE * 2) + u * 16) =
                gq[(size_t)r * 48 + u];
        }
    }

    issue_b_chunk(sbB, tid, 0, rule0);
    issue_b_chunk(sbB, tid, 1, rule0);

    // ldmatrix lane addressing (element units)
    const int a_row = (lane & 15);
    const int a_kof = (lane >> 4) << 3;
    const int b_row = ((lane >> 4) << 3) + (lane & 7);
    const int b_kof = ((lane >> 3) & 1) << 3;

    volatile float* vthr = sm->thr;
    uint32_t c[2][8][2];   // f16x2 accumulators: [mi][nq][h]

    int t = 0, kc = 0;
    for (int ch = 0; ch < TOT; ++ch) {
        if (kc == 0) {
            #pragma unroll
            for (int mi = 0; mi < 2; ++mi)
                #pragma unroll
                for (int nq = 0; nq < 8; ++nq) { c[mi][nq][0] = 0u; c[mi][nq][1] = 0u; }
        }

        if (ch == TOT - 1)
            asm volatile("cp.async.wait_group 0;" ::: "memory");
        else
            asm volatile("cp.async.wait_group 1;" ::: "memory");
        __syncthreads();

        if (ch + 2 < TOT) issue_b_chunk(sbB, tid, ch + 2, rule0);

        const uint32_t bB = sbB + (uint32_t)(ch % 3) * (BN * BSTRIDE * 2);
        const int k0 = kc * BK;

        #pragma unroll
        for (int ks = 0; ks < 4; ++ks) {
            const int k = k0 + ks * 16;
            uint32_t a[2][4];
            #pragma unroll
            for (int mi = 0; mi < 2; ++mi)
                ldsm_x4(a[mi], sbA + (uint32_t)((wm + mi * 16 + a_row) * ASTRIDE + k + a_kof) * 2);
            uint32_t b[4][4];
            #pragma unroll
            for (int nt = 0; nt < 4; ++nt)
                ldsm_x4(b[nt], bB + (uint32_t)((wn + nt * 16 + b_row) * BSTRIDE + ks * 16 + b_kof) * 2);
            #pragma unroll
            for (int mi = 0; mi < 2; ++mi)
                #pragma unroll
                for (int nq = 0; nq < 8; ++nq)
                    mma16816_f16(c[mi][nq], a[mi],
                                 b[nq >> 1][(nq & 1) * 2], b[nq >> 1][(nq & 1) * 2 + 1]);
        }

        if (kc == KCH - 1) {
            const int jb = rule0 + t * BN;
            #pragma unroll
            for (int mi = 0; mi < 2; ++mi) {
                #pragma unroll
                for (int h = 0; h < 2; ++h) {
                    const int r = wm + mi * 16 + (lane >> 2) + h * 8;
                    float cthr = vthr[r];   // monotone: stale => only extra inserts
                    #pragma unroll
                    for (int nq = 0; nq < 8; ++nq) {
                        __half2 h2 = *reinterpret_cast<__half2*>(&c[mi][nq][h]);
                        float2 vf = __half22float2(h2);
                        int j0 = jb + wn + nq * 8 + (lane & 3) * 2;
                        if (vf.x > cthr && j0 < N_RULES) {
                            topk_insert(sm, r, vf.x, j0);
                            cthr = vthr[r];
                        }
                        if (vf.y > cthr && j0 + 1 < N_RULES) {
                            topk_insert(sm, r, vf.y, j0 + 1);
                            cthr = vthr[r];
                        }
                    }
                }
            }
        }

        if (++kc == KCH) { kc = 0; ++t; }
    }
    __syncthreads();

    // write per-row candidate indices (this half's top-16)
    for (int i = tid; i < BM * TOPK_C; i += NTHREADS) {
        int r = i / TOPK_C, p = i - (i / TOPK_C) * TOPK_C;
        g_topi[(size_t)(row0 + r) * NCAND + half * TOPK_C + p] = sm->topi[i];
    }
}

// ---------------- refine: exact fp32 sims on 32 candidates -> top-8 --------
__global__ __launch_bounds__(256)
void refine_kernel(const float* __restrict__ emb, const float* __restrict__ rules) {
    __shared__ float sims[8][NCAND];
    const int w = threadIdx.x >> 5, lane = threadIdx.x & 31;
    const int row = blockIdx.x * 8 + w;

    const float* e = emb + (size_t)row * D_DIM;
    float er[12];
    #pragma unroll
    for (int i = 0; i < 12; ++i) er[i] = e[lane + 32 * i];
    const float qi = g_qinv[row];

    for (int cnd = 0; cnd < NCAND; ++cnd) {
        int idx = g_topi[(size_t)row * NCAND + cnd];
        const float* rr = rules + (size_t)idx * D_DIM;
        float acc = 0.0f;
        #pragma unroll
        for (int i = 0; i < 12; ++i) acc += er[i] * rr[lane + 32 * i];
        for (int o = 16; o; o >>= 1) acc += __shfl_xor_sync(0xffffffffu, acc, o);
        if (lane == 0) sims[w][cnd] = acc * qi * g_rinv[idx];
    }
    __syncwarp();

    if (lane == 0) {
        float s[NCAND];
        #pragma unroll
        for (int q = 0; q < NCAND; ++q) s[q] = sims[w][q];
        float v[TOPK]; int id8[TOPK];
        #pragma unroll
        for (int p = 0; p < TOPK; ++p) {
            float bm = -FLT_MAX; int bq = 0;
            #pragma unroll
            for (int q = 0; q < NCAND; ++q)
                if (s[q] > bm) { bm = s[q]; bq = q; }
            v[p] = bm;
            id8[p] = g_topi[(size_t)row * NCAND + bq];
            s[bq] = -FLT_MAX;
        }
        float m = v[0];
        float ssum = 0.0f;
        float ex[TOPK];
        #pragma unroll
        for (int p = 0; p < TOPK; ++p) { ex[p] = expf(v[p] - m); ssum += ex[p]; }
        float inv = 1.0f / ssum;
        #pragma unroll
        for (int p = 0; p < TOPK; ++p) {
            g_w8f[(size_t)row * TOPK + p] = ex[p] * inv;
            g_i8f[(size_t)row * TOPK + p] = id8[p];
        }
    }
}

// ---------------- epilogue: gather -> gelu(Wx+b) -> LN ---------------------
#define ER 16
__global__ __launch_bounds__(256)
void epilogue_kernel(const float* __restrict__ s0,
                     const float* __restrict__ rules_raw,
                     const float* __restrict__ W,
                     const float* __restrict__ bvec,
                     const float* __restrict__ alpha_p,
                     const float* __restrict__ gamma,
                     const float* __restrict__ beta,
                     float* __restrict__ out) {
    __shared__ float ctx[ER][D_DIM];
    __shared__ float xs[ER][H_DIM];
    __shared__ float w8[ER][TOPK];
    __shared__ int   i8[ER][TOPK];
    __shared__ float mu_s[ER], rs_s[ER];

    const int tid = threadIdx.x;  // 256
    const int r0  = blockIdx.x * ER;

    for (int e = tid; e < ER * TOPK; e += 256) {
        int r = e >> 3, p = e & 7;
        w8[r][p] = g_w8f[(size_t)(r0 + r) * TOPK + p];
        i8[r][p] = g_i8f[(size_t)(r0 + r) * TOPK + p];
    }
    __syncthreads();

    for (int e = tid; e < ER * D_DIM; e += 256) {
        int r = e / D_DIM, d = e - r * D_DIM;
        float acc = 0.0f;
        #pragma unroll
        for (int k = 0; k < TOPK; ++k) {
            int idx = i8[r][k];
            acc += w8[r][k] * rules_raw[(size_t)idx * D_DIM + d] * g_rinv[idx];
        }
        ctx[r][d] = acc;
    }
    __syncthreads();

    const float alpha = *alpha_p;
    const int h = tid;
    float acc[ER];
    #pragma unroll
    for (int r = 0; r < ER; ++r) acc[r] = 0.0f;

    const float4* wr = reinterpret_cast<const float4*>(W + (size_t)h * D_DIM);
    #pragma unroll 4
    for (int dq = 0; dq < D_DIM / 4; ++dq) {
        float4 w4 = wr[dq];
        #pragma unroll
        for (int r = 0; r < ER; ++r) {
            float4 c4 = *reinterpret_cast<const float4*>(&ctx[r][dq * 4]);
            acc[r] += w4.x * c4.x + w4.y * c4.y + w4.z * c4.z + w4.w * c4.w;
        }
    }
    const float bb = bvec[h];
    #pragma unroll
    for (int r = 0; r < ER; ++r) {
        float z = acc[r] + bb;
        float g = 0.5f * z * (1.0f + erff(z * 0.70710678118654752f));
        xs[r][h] = s0[(size_t)(r0 + r) * H_DIM + h] + alpha * g;
    }
    __syncthreads();

    const int w = tid >> 5, lane = tid & 31;
    for (int rr = w; rr < ER; rr += 8) {
        float s = 0.0f, s2 = 0.0f;
        #pragma unroll
        for (int q = 0; q < 8; ++q) {
            float x = xs[rr][lane + 32 * q];
            s += x; s2 += x * x;
        }
        for (int o = 16; o; o >>= 1) {
            s  += __shfl_xor_sync(0xffffffffu, s, o);
            s2 += __shfl_xor_sync(0xffffffffu, s2, o);
        }
        if (lane == 0) {
            float mu  = s * (1.0f / 256.0f);
            float var = s2 * (1.0f / 256.0f) - mu * mu;
            mu_s[rr] = mu;
            rs_s[rr] = rsqrtf(var + 1e-5f);
        }
    }
    __syncthreads();

    const float gm = gamma[h], bt = beta[h];
    #pragma unroll
    for (int r = 0; r < ER; ++r)
        out[(size_t)(r0 + r) * H_DIM + h] = (xs[r][h] - mu_s[r]) * rs_s[r] * gm + bt;
}

// ---------------- launch ----------------------------------------------------
extern "C" void kernel_launch(void* const* d_in, const int* in_sizes, int n_in,
                              void* d_out, int out_size) {
    const float* embeddings = (const float*)d_in[0];
    const float* s0         = (const float*)d_in[1];
    const float* rules      = (const float*)d_in[2];
    const float* W          = (const float*)d_in[3];
    const float* b          = (const float*)d_in[4];
    const float* alpha      = (const float*)d_in[5];
    const float* gamma      = (const float*)d_in[6];
    const float* beta       = (const float*)d_in[7];
    float* out = (float*)d_out;
    (void)in_sizes; (void)n_in; (void)out_size;

    cudaFuncSetAttribute(sims_topk_kernel,
                         cudaFuncAttributeMaxDynamicSharedMemorySize,
                         (int)sizeof(SimsSmem));

    prep_rules_kernel<<<N_PAD, 128>>>(rules);
    prep_q_kernel<<<B_ROWS, 128>>>(embeddings);
    sims_topk_kernel<<<128, NTHREADS, sizeof(SimsSmem)>>>();
    refine_kernel<<<B_ROWS / 8, 256>>>(embeddings, rules);
    epilogue_kernel<<<B_ROWS / ER, 256>>>(s0, rules, W, b, alpha, gamma, beta, out);
}

// round 7
// speedup vs baseline: 1.0311x; 1.0311x over previous
#include <cuda_runtime.h>
#include <cuda_bf16.h>
#include <math.h>
#include <stdint.h>
#include <float.h>

#define N_RULES 50000
#define N_PAD   50176            // 196 * 256
#define NHALF   25088            // rules per CTA-half
#define TILES   98               // NHALF / 256
#define D_DIM   384
#define B_ROWS  8192
#define H_DIM   256
#define TOPK    8
#define TOPK_C  16               // coarse candidates per half
#define NCAND   32               // 2 halves * 16

#define BM 128
#define BN 256
#define BK 64
#define KCH 6                    // 384 / 64
#define TOT (TILES * KCH)        // 588
#define ASTRIDE 392              // elems: 384 + 8 (conflict-free LDSM)
#define BSTRIDE 72               // elems: 64 + 8
#define NTHREADS 512

// ---------------- device scratch ----------------
__device__ __nv_bfloat16 g_rb[(size_t)N_PAD * D_DIM];
__device__ float  g_rinv[N_PAD];
__device__ __nv_bfloat16 g_qb[(size_t)B_ROWS * D_DIM];
__device__ float  g_qinv[B_ROWS];
__device__ int    g_topi[(size_t)B_ROWS * NCAND];
__device__ float  g_w8f[(size_t)B_ROWS * TOPK];
__device__ int    g_i8f[(size_t)B_ROWS * TOPK];

// ---------------- smem struct ----------------
struct __align__(16) SimsSmem {
    __nv_bfloat16 As[BM * ASTRIDE];     // 100352 B
    __nv_bfloat16 Bs[3][BN * BSTRIDE];  // 110592 B
    float topv[BM * TOPK_C];            // 8192 B
    int   topi[BM * TOPK_C];            // 8192 B
    float thr[BM];
    int   lck[BM];
};                                      // 228352 B

// ---------------- PTX helpers ----------------
__device__ __forceinline__ uint32_t smem_u32(const void* p) {
    uint32_t a;
    asm("{ .reg .u64 t; cvta.to.shared.u64 t, %1; cvt.u32.u64 %0, t; }" : "=r"(a) : "l"(p));
    return a;
}
__device__ __forceinline__ void cp16(uint32_t dst, const void* src) {
    asm volatile("cp.async.cg.shared.global [%0], [%1], 16;" :: "r"(dst), "l"(src));
}
__device__ __forceinline__ void ldsm_x4(uint32_t* r, uint32_t addr) {
    asm volatile("ldmatrix.sync.aligned.m8n8.x4.shared.b16 {%0,%1,%2,%3}, [%4];"
                 : "=r"(r[0]), "=r"(r[1]), "=r"(r[2]), "=r"(r[3]) : "r"(addr));
}
__device__ __forceinline__ void mma16816(float* c, const uint32_t* a,
                                         uint32_t b0, uint32_t b1) {
    asm volatile(
        "mma.sync.aligned.m16n8k16.row.col.f32.bf16.bf16.f32 "
        "{%0,%1,%2,%3}, {%4,%5,%6,%7}, {%8,%9}, {%0,%1,%2,%3};\n"
        : "+f"(c[0]), "+f"(c[1]), "+f"(c[2]), "+f"(c[3])
        : "r"(a[0]), "r"(a[1]), "r"(a[2]), "r"(a[3]), "r"(b0), "r"(b1));
}

// ---------------- prep kernels: normalize + bf16 cast -----------------------
__global__ void prep_rules_kernel(const float* __restrict__ src) {
    int row = blockIdx.x;
    int tid = threadIdx.x;  // 128
    if (row >= N_RULES) {
        for (int d = tid; d < D_DIM; d += 128)
            g_rb[(size_t)row * D_DIM + d] = __float2bfloat16(0.0f);
        if (tid == 0) g_rinv[row] = 0.0f;
        return;
    }
    const float* x = src + (size_t)row * D_DIM;
    float s = 0.0f;
    for (int d = tid; d < D_DIM; d += 128) { float v = x[d]; s += v * v; }
    __shared__ float red[4];
    for (int o = 16; o; o >>= 1) s += __shfl_xor_sync(0xffffffffu, s, o);
    if ((tid & 31) == 0) red[tid >> 5] = s;
    __syncthreads();
    if (tid == 0) {
        float t = red[0] + red[1] + red[2] + red[3];
        red[0] = 1.0f / fmaxf(sqrtf(t), 1e-12f);
    }
    __syncthreads();
    float inv = red[0];
    for (int d = tid; d < D_DIM; d += 128)
        g_rb[(size_t)row * D_DIM + d] = __float2bfloat16(x[d] * inv);
    if (tid == 0) g_rinv[row] = inv;
}

__global__ void prep_q_kernel(const float* __restrict__ src) {
    int row = blockIdx.x;
    int tid = threadIdx.x;  // 128
    const float* x = src + (size_t)row * D_DIM;
    float s = 0.0f;
    for (int d = tid; d < D_DIM; d += 128) { float v = x[d]; s += v * v; }
    __shared__ float red[4];
    for (int o = 16; o; o >>= 1) s += __shfl_xor_sync(0xffffffffu, s, o);
    if ((tid & 31) == 0) red[tid >> 5] = s;
    __syncthreads();
    if (tid == 0) {
        float t = red[0] + red[1] + red[2] + red[3];
        red[0] = 1.0f / fmaxf(sqrtf(t), 1e-12f);
    }
    __syncthreads();
    float inv = red[0];
    for (int d = tid; d < D_DIM; d += 128)
        g_qb[(size_t)row * D_DIM + d] = __float2bfloat16(x[d] * inv);
    if (tid == 0) g_qinv[row] = inv;
}

// ---------------- fused bf16 sims GEMM + streaming coarse top-16 -----------
__device__ __forceinline__ void issue_b_chunk(uint32_t sbB, int tid, int ch, int rule0) {
    int t  = ch / KCH;
    int kc = ch - t * KCH;
    const __nv_bfloat16* src = g_rb + ((size_t)rule0 + (size_t)t * BN) * D_DIM + kc * BK;
    uint32_t bbase = sbB + (uint32_t)(ch % 3) * (BN * BSTRIDE * 2);
    #pragma unroll
    for (int i = 0; i < 4; ++i) {   // 256 rows * 8 uint4 = 2048 / 512 thr
        int e = tid + i * NTHREADS;
        int r = e >> 3;
        int u = e & 7;
        cp16(bbase + (uint32_t)(r * BSTRIDE + u * 8) * 2, src + (size_t)r * D_DIM + u * 8);
    }
    asm volatile("cp.async.commit_group;" ::: "memory");
}

__device__ void topk_insert(SimsSmem* sm, int r, float v, int j) {
    bool done = false;
    while (!done) {
        if (atomicCAS(&sm->lck[r], 0, 1) == 0) {
            volatile float* tv = sm->topv + r * TOPK_C;
            volatile int*   ti = sm->topi + r * TOPK_C;
            float mn = tv[0]; int mp = 0;
            #pragma unroll
            for (int p = 1; p < TOPK_C; ++p) { float x = tv[p]; if (x < mn) { mn = x; mp = p; } }
            if (v > mn) {
                tv[mp] = v;
                ti[mp] = j;
                float nm = v;
                #pragma unroll
                for (int p = 0; p < TOPK_C; ++p) { float x = tv[p]; if (x < nm) nm = x; }
                sm->thr[r] = nm;
            }
            __threadfence_block();
            atomicExch(&sm->lck[r], 0);
            done = true;
        }
    }
}

__global__ __launch_bounds__(NTHREADS, 1)
void sims_topk_kernel() {
    extern __shared__ char smraw[];
    SimsSmem* sm = reinterpret_cast<SimsSmem*>(smraw);
    const uint32_t sbA = smem_u32(sm->As);
    const uint32_t sbB = smem_u32(sm->Bs);

    const int tid    = threadIdx.x;
    const int lane   = tid & 31;
    const int wid    = tid >> 5;            // 0..15
    const int wm     = (wid & 3) * 32;      // 4 m-warps over 128 rows
    const int wn     = (wid >> 2) * 64;     // 4 n-warps over 256 cols
    const int grp    = blockIdx.x >> 1;
    const int half   = blockIdx.x & 1;
    const int row0   = grp * BM;
    const int rule0  = half * NHALF;

    for (int i = tid; i < BM * TOPK_C; i += NTHREADS) { sm->topv[i] = -FLT_MAX; sm->topi[i] = 0; }
    for (int i = tid; i < BM; i += NTHREADS)          { sm->thr[i]  = -FLT_MAX; sm->lck[i]  = 0; }

    // resident A: 128 rows x 384 bf16
    {
        const uint4* gq = reinterpret_cast<const uint4*>(g_qb + (size_t)row0 * D_DIM);
        for (int i = tid; i < BM * 48; i += NTHREADS) {
            int r = i / 48, u = i - (i / 48) * 48;
            *reinterpret_cast<uint4*>(
                reinterpret_cast<char*>(sm->As) + (size_t)r * (ASTRIDE * 2) + u * 16) =
                gq[(size_t)r * 48 + u];
        }
    }

    issue_b_chunk(sbB, tid, 0, rule0);
    issue_b_chunk(sbB, tid, 1, rule0);

    // ldmatrix lane addressing (element units)
    const int a_row = (lane & 15);
    const int a_kof = (lane >> 4) << 3;
    const int b_row = ((lane >> 4) << 3) + (lane & 7);
    const int b_kof = ((lane >> 3) & 1) << 3;

    volatile float* vthr = sm->thr;
    float c[2][8][4];

    int t = 0, kc = 0;
    for (int ch = 0; ch < TOT; ++ch) {
        if (kc == 0) {
            #pragma unroll
            for (int mi = 0; mi < 2; ++mi)
                #pragma unroll
                for (int nq = 0; nq < 8; ++nq)
                    #pragma unroll
                    for (int e = 0; e < 4; ++e) c[mi][nq][e] = 0.0f;
        }

        if (ch == TOT - 1)
            asm volatile("cp.async.wait_group 0;" ::: "memory");
        else
            asm volatile("cp.async.wait_group 1;" ::: "memory");
        __syncthreads();

        if (ch + 2 < TOT) issue_b_chunk(sbB, tid, ch + 2, rule0);

        const uint32_t bB = sbB + (uint32_t)(ch % 3) * (BN * BSTRIDE * 2);
        const int k0 = kc * BK;

        #pragma unroll
        for (int ks = 0; ks < 4; ++ks) {
            const int k = k0 + ks * 16;
            uint32_t a[2][4];
            #pragma unroll
            for (int mi = 0; mi < 2; ++mi)
                ldsm_x4(a[mi], sbA + (uint32_t)((wm + mi * 16 + a_row) * ASTRIDE + k + a_kof) * 2);
            uint32_t b[4][4];
            #pragma unroll
            for (int nt = 0; nt < 4; ++nt)
                ldsm_x4(b[nt], bB + (uint32_t)((wn + nt * 16 + b_row) * BSTRIDE + ks * 16 + b_kof) * 2);
            #pragma unroll
            for (int mi = 0; mi < 2; ++mi)
                #pragma unroll
                for (int nq = 0; nq < 8; ++nq)
                    mma16816(c[mi][nq], a[mi],
                             b[nq >> 1][(nq & 1) * 2], b[nq >> 1][(nq & 1) * 2 + 1]);
        }

        if (kc == KCH - 1) {
            const int jb = rule0 + t * BN;
            #pragma unroll
            for (int mi = 0; mi < 2; ++mi) {
                #pragma unroll
                for (int h = 0; h < 2; ++h) {
                    const int r = wm + mi * 16 + (lane >> 2) + h * 8;
                    float cthr = vthr[r];   // monotone: stale => only extra inserts
                    #pragma unroll
                    for (int nq = 0; nq < 8; ++nq) {
                        #pragma unroll
                        for (int e = 0; e < 2; ++e) {
                            float v = c[mi][nq][h * 2 + e];
                            int j = jb + wn + nq * 8 + (lane & 3) * 2 + e;
                            if (v > cthr && j < N_RULES) {
                                topk_insert(sm, r, v, j);
                                cthr = vthr[r];
                            }
                        }
                    }
                }
            }
        }

        if (++kc == KCH) { kc = 0; ++t; }
    }
    __syncthreads();

    // write per-row candidate indices (this half's top-16)
    for (int i = tid; i < BM * TOPK_C; i += NTHREADS) {
        int r = i / TOPK_C, p = i - (i / TOPK_C) * TOPK_C;
        g_topi[(size_t)(row0 + r) * NCAND + half * TOPK_C + p] = sm->topi[i];
    }
}

// ---------------- refine: exact fp32 sims on 32 candidates -> top-8 --------
__global__ __launch_bounds__(256)
void refine_kernel(const float* __restrict__ emb, const float* __restrict__ rules) {
    __shared__ float sims[8][NCAND];
    const int w = threadIdx.x >> 5, lane = threadIdx.x & 31;
    const int row = blockIdx.x * 8 + w;

    const float* e = emb + (size_t)row * D_DIM;
    float er[12];
    #pragma unroll
    for (int i = 0; i < 12; ++i) er[i] = e[lane + 32 * i];
    const float qi = g_qinv[row];

    for (int cnd = 0; cnd < NCAND; ++cnd) {
        int idx = g_topi[(size_t)row * NCAND + cnd];
        const float* rr = rules + (size_t)idx * D_DIM;
        float acc = 0.0f;
        #pragma unroll
        for (int i = 0; i < 12; ++i) acc += er[i] * rr[lane + 32 * i];
        for (int o = 16; o; o >>= 1) acc += __shfl_xor_sync(0xffffffffu, acc, o);
        if (lane == 0) sims[w][cnd] = acc * qi * g_rinv[idx];
    }
    __syncwarp();

    if (lane == 0) {
        float s[NCAND];
        #pragma unroll
        for (int q = 0; q < NCAND; ++q) s[q] = sims[w][q];
        float v[TOPK]; int id8[TOPK];
        #pragma unroll
        for (int p = 0; p < TOPK; ++p) {
            float bm = -FLT_MAX; int bq = 0;
            #pragma unroll
            for (int q = 0; q < NCAND; ++q)
                if (s[q] > bm) { bm = s[q]; bq = q; }
            v[p] = bm;
            id8[p] = g_topi[(size_t)row * NCAND + bq];
            s[bq] = -FLT_MAX;
        }
        float m = v[0];
        float ssum = 0.0f;
        float ex[TOPK];
        #pragma unroll
        for (int p = 0; p < TOPK; ++p) { ex[p] = expf(v[p] - m); ssum += ex[p]; }
        float inv = 1.0f / ssum;
        #pragma unroll
        for (int p = 0; p < TOPK; ++p) {
            g_w8f[(size_t)row * TOPK + p] = ex[p] * inv;
            g_i8f[(size_t)row * TOPK + p] = id8[p];
        }
    }
}

// ---------------- epilogue: gather -> gelu(Wx+b) -> LN ---------------------
#define ER 16
__global__ __launch_bounds__(256)
void epilogue_kernel(const float* __restrict__ s0,
                     const float* __restrict__ rules_raw,
                     const float* __restrict__ W,
                     const float* __restrict__ bvec,
                     const float* __restrict__ alpha_p,
                     const float* __restrict__ gamma,
                     const float* __restrict__ beta,
                     float* __restrict__ out) {
    __shared__ float ctx[ER][D_DIM];
    __shared__ float xs[ER][H_DIM];
    __shared__ float w8[ER][TOPK];
    __shared__ int   i8[ER][TOPK];
    __shared__ float mu_s[ER], rs_s[ER];

    const int tid = threadIdx.x;  // 256
    const int r0  = blockIdx.x * ER;

    for (int e = tid; e < ER * TOPK; e += 256) {
        int r = e >> 3, p = e & 7;
        w8[r][p] = g_w8f[(size_t)(r0 + r) * TOPK + p];
        i8[r][p] = g_i8f[(size_t)(r0 + r) * TOPK + p];
    }
    __syncthreads();

    for (int e = tid; e < ER * D_DIM; e += 256) {
        int r = e / D_DIM, d = e - r * D_DIM;
        float acc = 0.0f;
        #pragma unroll
        for (int k = 0; k < TOPK; ++k) {
            int idx = i8[r][k];
            acc += w8[r][k] * rules_raw[(size_t)idx * D_DIM + d] * g_rinv[idx];
        }
        ctx[r][d] = acc;
    }
    __syncthreads();

    const float alpha = *alpha_p;
    const int h = tid;
    float acc[ER];
    #pragma unroll
    for (int r = 0; r < ER; ++r) acc[r] = 0.0f;

    const float4* wr = reinterpret_cast<const float4*>(W + (size_t)h * D_DIM);
    #pragma unroll 4
    for (int dq = 0; dq < D_DIM / 4; ++dq) {
        float4 w4 = wr[dq];
        #pragma unroll
        for (int r = 0; r < ER; ++r) {
            float4 c4 = *reinterpret_cast<const float4*>(&ctx[r][dq * 4]);
            acc[r] += w4.x * c4.x + w4.y * c4.y + w4.z * c4.z + w4.w * c4.w;
        }
    }
    const float bb = bvec[h];
    #pragma unroll
    for (int r = 0; r < ER; ++r) {
        float z = acc[r] + bb;
        float g = 0.5f * z * (1.0f + erff(z * 0.70710678118654752f));
        xs[r][h] = s0[(size_t)(r0 + r) * H_DIM + h] + alpha * g;
    }
    __syncthreads();

    const int w = tid >> 5, lane = tid & 31;
    for (int rr = w; rr < ER; rr += 8) {
        float s = 0.0f, s2 = 0.0f;
        #pragma unroll
        for (int q = 0; q < 8; ++q) {
            float x = xs[rr][lane + 32 * q];
            s += x; s2 += x * x;
        }
        for (int o = 16; o; o >>= 1) {
            s  += __shfl_xor_sync(0xffffffffu, s, o);
            s2 += __shfl_xor_sync(0xffffffffu, s2, o);
        }
        if (lane == 0) {
            float mu  = s * (1.0f / 256.0f);
            float var = s2 * (1.0f / 256.0f) - mu * mu;
            mu_s[rr] = mu;
            rs_s[rr] = rsqrtf(var + 1e-5f);
        }
    }
    __syncthreads();

    const float gm = gamma[h], bt = beta[h];
    #pragma unroll
    for (int r = 0; r < ER; ++r)
        out[(size_t)(r0 + r) * H_DIM + h] = (xs[r][h] - mu_s[r]) * rs_s[r] * gm + bt;
}

// ---------------- launch ----------------------------------------------------
extern "C" void kernel_launch(void* const* d_in, const int* in_sizes, int n_in,
                              void* d_out, int out_size) {
    const float* embeddings = (const float*)d_in[0];
    const float* s0         = (const float*)d_in[1];
    const float* rules      = (const float*)d_in[2];
    const float* W          = (const float*)d_in[3];
    const float* b          = (const float*)d_in[4];
    const float* alpha      = (const float*)d_in[5];
    const float* gamma      = (const float*)d_in[6];
    const float* beta       = (const float*)d_in[7];
    float* out = (float*)d_out;
    (void)in_sizes; (void)n_in; (void)out_size;

    cudaFuncSetAttribute(sims_topk_kernel,
                         cudaFuncAttributeMaxDynamicSharedMemorySize,
                         (int)sizeof(SimsSmem));

    prep_rules_kernel<<<N_PAD, 128>>>(rules);
    prep_q_kernel<<<B_ROWS, 128>>>(embeddings);
    sims_topk_kernel<<<128, NTHREADS, sizeof(SimsSmem)>>>();
    refine_kernel<<<B_ROWS / 8, 256>>>(embeddings, rules);
    epilogue_kernel<<<B_ROWS / ER, 256>>>(s0, rules, W, b, alpha, gamma, beta, out);
}

// round 8
// speedup vs baseline: 1.3286x; 1.2884x over previous
#include <cuda_runtime.h>
#include <cuda_bf16.h>
#include <math.h>
#include <stdint.h>
#include <float.h>

#define N_RULES 50000
#define N_PAD   50176            // 392 * 128
#define D_DIM   384
#define B_ROWS  8192
#define H_DIM   256
#define TOPK    8
#define TOPK_C  16               // coarse candidates per section
#define SLOTS   4                // max sections per (row-group)
#define NCANDT  (SLOTS * TOPK_C) // 64 candidate slots per row

#define BM 128
#define BN 128
#define BK 128                   // elems per K-chunk
#define KCH 3                    // 384 / 128
#define GTILES 392               // rule tiles per group (N_PAD / BN)
#define NUNITS (64 * GTILES)     // 25088 tile-units total
#define NCTAS  148
#define ASTRIDE 392              // elems: 384 + 8  (784B row, LDSM conflict-free)
#define BSTRIDE 136              // elems: 128 + 8  (272B row, LDSM conflict-free)
#define NTHREADS 512

// ---------------- device scratch ----------------
__device__ __nv_bfloat16 g_rb[(size_t)N_PAD * D_DIM];
__device__ float  g_rinv[N_PAD];
__device__ __nv_bfloat16 g_qb[(size_t)B_ROWS * D_DIM];
__device__ float  g_qinv[B_ROWS];
__device__ float  g_cand_v[(size_t)B_ROWS * NCANDT];   // zero-init .bss; unwritten slots stay 0
__device__ int    g_cand_i[(size_t)B_ROWS * NCANDT];
__device__ float  g_w8f[(size_t)B_ROWS * TOPK];
__device__ int    g_i8f[(size_t)B_ROWS * TOPK];

// ---------------- smem struct ----------------
struct __align__(16) SimsSmem {
    __nv_bfloat16 As[BM * ASTRIDE];     // 100352 B
    __nv_bfloat16 Bs[3][BN * BSTRIDE];  // 104448 B
    float topv[BM * TOPK_C];            // 8192 B
    int   topi[BM * TOPK_C];            // 8192 B
    float thr[BM];                      // 512 B
    int   lck[BM];                      // 512 B
};                                      // 222208 B

// ---------------- PTX helpers ----------------
__device__ __forceinline__ uint32_t smem_u32(const void* p) {
    uint32_t a;
    asm("{ .reg .u64 t; cvta.to.shared.u64 t, %1; cvt.u32.u64 %0, t; }" : "=r"(a) : "l"(p));
    return a;
}
__device__ __forceinline__ void cp16(uint32_t dst, const void* src) {
    asm volatile("cp.async.cg.shared.global [%0], [%1], 16;" :: "r"(dst), "l"(src));
}
__device__ __forceinline__ void ldsm_x4(uint32_t* r, uint32_t addr) {
    asm volatile("ldmatrix.sync.aligned.m8n8.x4.shared.b16 {%0,%1,%2,%3}, [%4];"
                 : "=r"(r[0]), "=r"(r[1]), "=r"(r[2]), "=r"(r[3]) : "r"(addr));
}
__device__ __forceinline__ void mma16816(float* c, const uint32_t* a,
                                         uint32_t b0, uint32_t b1) {
    asm volatile(
        "mma.sync.aligned.m16n8k16.row.col.f32.bf16.bf16.f32 "
        "{%0,%1,%2,%3}, {%4,%5,%6,%7}, {%8,%9}, {%0,%1,%2,%3};\n"
        : "+f"(c[0]), "+f"(c[1]), "+f"(c[2]), "+f"(c[3])
        : "r"(a[0]), "r"(a[1]), "r"(a[2]), "r"(a[3]), "r"(b0), "r"(b1));
}
__device__ __forceinline__ int ustart(int c) { return c * 169 + (c < 76 ? c : 76); }

// ---------------- prep kernels: normalize + bf16 cast ----------------------
__global__ void prep_rules_kernel(const float* __restrict__ src) {
    int row = blockIdx.x;
    int tid = threadIdx.x;  // 128
    if (row >= N_RULES) {
        for (int d = tid; d < D_DIM; d += 128)
            g_rb[(size_t)row * D_DIM + d] = __float2bfloat16(0.0f);
        if (tid == 0) g_rinv[row] = 0.0f;
        return;
    }
    const float* x = src + (size_t)row * D_DIM;
    float s = 0.0f;
    for (int d = tid; d < D_DIM; d += 128) { float v = x[d]; s += v * v; }
    __shared__ float red[4];
    for (int o = 16; o; o >>= 1) s += __shfl_xor_sync(0xffffffffu, s, o);
    if ((tid & 31) == 0) red[tid >> 5] = s;
    __syncthreads();
    if (tid == 0) {
        float t = red[0] + red[1] + red[2] + red[3];
        red[0] = 1.0f / fmaxf(sqrtf(t), 1e-12f);
    }
    __syncthreads();
    float inv = red[0];
    for (int d = tid; d < D_DIM; d += 128)
        g_rb[(size_t)row * D_DIM + d] = __float2bfloat16(x[d] * inv);
    if (tid == 0) g_rinv[row] = inv;
}

__global__ void prep_q_kernel(const float* __restrict__ src) {
    int row = blockIdx.x;
    int tid = threadIdx.x;  // 128
    const float* x = src + (size_t)row * D_DIM;
    float s = 0.0f;
    for (int d = tid; d < D_DIM; d += 128) { float v = x[d]; s += v * v; }
    __shared__ float red[4];
    for (int o = 16; o; o >>= 1) s += __shfl_xor_sync(0xffffffffu, s, o);
    if ((tid & 31) == 0) red[tid >> 5] = s;
    __syncthreads();
    if (tid == 0) {
        float t = red[0] + red[1] + red[2] + red[3];
        red[0] = 1.0f / fmaxf(sqrtf(t), 1e-12f);
    }
    __syncthreads();
    float inv = red[0];
    for (int d = tid; d < D_DIM; d += 128)
        g_qb[(size_t)row * D_DIM + d] = __float2bfloat16(x[d] * inv);
    if (tid == 0) g_qinv[row] = inv;
}

// ---------------- persistent fused sims GEMM + streaming coarse top-16 -----
__device__ __forceinline__ void issue_b_chunk(uint32_t sbB, int tid, int tile,
                                              int kc, int stage) {
    const __nv_bfloat16* src = g_rb + (size_t)tile * (BN * D_DIM) + kc * BK;
    uint32_t bbase = sbB + (uint32_t)stage * (BN * BSTRIDE * 2);
    #pragma unroll
    for (int i = 0; i < 4; ++i) {   // 128 rows * 16 uint4 = 2048 / 512 thr
        int e = tid + i * NTHREADS;
        int r = e >> 4;
        int u = e & 15;
        cp16(bbase + (uint32_t)(r * BSTRIDE + u * 8) * 2, src + (size_t)r * D_DIM + u * 8);
    }
    asm volatile("cp.async.commit_group;" ::: "memory");
}

__device__ void topk_insert(SimsSmem* sm, int r, float v, int j) {
    bool done = false;
    while (!done) {
        if (atomicCAS(&sm->lck[r], 0, 1) == 0) {
            volatile float* tv = sm->topv + r * TOPK_C;
            volatile int*   ti = sm->topi + r * TOPK_C;
            float mn = tv[0]; int mp = 0;
            #pragma unroll
            for (int p = 1; p < TOPK_C; ++p) { float x = tv[p]; if (x < mn) { mn = x; mp = p; } }
            if (v > mn) {
                tv[mp] = v;
                ti[mp] = j;
                float nm = v;
                #pragma unroll
                for (int p = 0; p < TOPK_C; ++p) { float x = tv[p]; if (x < nm) nm = x; }
                sm->thr[r] = nm;
            }
            __threadfence_block();
            atomicExch(&sm->lck[r], 0);
            done = true;
        }
    }
}

__global__ __launch_bounds__(NTHREADS, 1)
void sims_topk_kernel() {
    extern __shared__ char smraw[];
    SimsSmem* sm = reinterpret_cast<SimsSmem*>(smraw);
    const uint32_t sbA = smem_u32(sm->As);
    const uint32_t sbB = smem_u32(sm->Bs);

    const int tid  = threadIdx.x;
    const int lane = tid & 31;
    const int wid  = tid >> 5;            // 0..15
    const int wm   = (wid & 3) * 32;      // 4 m-warps over 128 rows
    const int wn   = (wid >> 2) * 32;     // 4 n-warps over 128 cols
    const int cta  = blockIdx.x;

    const int u0 = ustart(cta);
    const int u1 = ustart(cta + 1);

    // ldmatrix lane addressing (element units)
    const int a_row = (lane & 15);
    const int a_kof = (lane >> 4) << 3;
    const int b_row = ((lane >> 4) << 3) + (lane & 7);
    const int b_kof = ((lane >> 3) & 1) << 3;

    volatile float* vthr = sm->thr;

    int u = u0;
    while (u < u1) {
        const int g    = u / GTILES;
        const int send = min(u1, (g + 1) * GTILES);
        const int t0   = u - g * GTILES;       // first tile in group
        const int nt   = send - u;
        const int row0 = g * BM;

        // slot id = index of this section within the group
        int c0 = (g * GTILES) / 170;
        while (ustart(c0 + 1) <= g * GTILES) ++c0;
        while (ustart(c0) > g * GTILES) --c0;
        const int slot = cta - c0;

        // init top-k state
        for (int i = tid; i < BM * TOPK_C; i += NTHREADS) { sm->topv[i] = -FLT_MAX; sm->topi[i] = 0; }
        for (int i = tid; i < BM; i += NTHREADS)          { sm->thr[i]  = -FLT_MAX; sm->lck[i]  = 0; }
        __syncthreads();   // smem (incl. prior section's Bs reads) quiesced

        // resident A for this group: 128 rows x 384 bf16 via cp.async (group 0)
        {
            const __nv_bfloat16* gq = g_qb + (size_t)row0 * D_DIM;
            #pragma unroll
            for (int i = 0; i < 12; ++i) {   // 128 rows * 48 uint4 / 512
                int e = tid + i * NTHREADS;
                int r = e / 48, uu = e - (e / 48) * 48;
                cp16(sbA + (uint32_t)(r * ASTRIDE + uu * 8) * 2, gq + (size_t)r * D_DIM + uu * 8);
            }
            asm volatile("cp.async.commit_group;" ::: "memory");
        }
        const int TOTC = nt * KCH;
        issue_b_chunk(sbB, tid, t0, 0, 0);
        if (TOTC > 1) issue_b_chunk(sbB, tid, t0 + (1 / KCH), 1 % KCH, 1);

        float c[2][4][4];
        int t = t0, kc = 0;
        for (int ch = 0; ch < TOTC; ++ch) {
            if (kc == 0) {
                #pragma unroll
                for (int mi = 0; mi < 2; ++mi)
                    #pragma unroll
                    for (int nq = 0; nq < 4; ++nq)
                        #pragma unroll
                        for (int e = 0; e < 4; ++e) c[mi][nq][e] = 0.0f;
            }

            if (ch >= TOTC - 2)
                asm volatile("cp.async.wait_group 0;" ::: "memory");
            else
                asm volatile("cp.async.wait_group 1;" ::: "memory");
            __syncthreads();

            if (ch + 2 < TOTC) {
                int ch2 = ch + 2;
                issue_b_chunk(sbB, tid, t0 + ch2 / KCH, ch2 % KCH, ch2 % 3);
            }

            const uint32_t bB = sbB + (uint32_t)(ch % 3) * (BN * BSTRIDE * 2);
            const int k0 = kc * BK;

            #pragma unroll
            for (int ks = 0; ks < 8; ++ks) {
                const int k = k0 + ks * 16;
                uint32_t a[2][4];
                #pragma unroll
                for (int mi = 0; mi < 2; ++mi)
                    ldsm_x4(a[mi], sbA + (uint32_t)((wm + mi * 16 + a_row) * ASTRIDE + k + a_kof) * 2);
                uint32_t b[2][4];
                #pragma unroll
                for (int nt2 = 0; nt2 < 2; ++nt2)
                    ldsm_x4(b[nt2], bB + (uint32_t)((wn + nt2 * 16 + b_row) * BSTRIDE + ks * 16 + b_kof) * 2);
                #pragma unroll
                for (int mi = 0; mi < 2; ++mi)
                    #pragma unroll
                    for (int nq = 0; nq < 4; ++nq)
                        mma16816(c[mi][nq], a[mi],
                                 b[nq >> 1][(nq & 1) * 2], b[nq >> 1][(nq & 1) * 2 + 1]);
            }

            if (kc == KCH - 1) {
                const int jb = t * BN;
                #pragma unroll
                for (int mi = 0; mi < 2; ++mi) {
                    #pragma unroll
                    for (int h = 0; h < 2; ++h) {
                        const int r = wm + mi * 16 + (lane >> 2) + h * 8;
                        float cthr = vthr[r];   // monotone: stale => only extra inserts
                        #pragma unroll
                        for (int nq = 0; nq < 4; ++nq) {
                            #pragma unroll
                            for (int e = 0; e < 2; ++e) {
                                float v = c[mi][nq][h * 2 + e];
                                int j = jb + wn + nq * 8 + (lane & 3) * 2 + e;
                                if (v > cthr && j < N_RULES) {
                                    topk_insert(sm, r, v, j);
                                    cthr = vthr[r];
                                }
                            }
                        }
                    }
                }
            }

            if (++kc == KCH) { kc = 0; ++t; }
        }
        __syncthreads();

        // write this section's per-row top-16 into its slot
        for (int i = tid; i < BM * TOPK_C; i += NTHREADS) {
            int r = i >> 4, p = i & 15;
            size_t o = (size_t)(row0 + r) * NCANDT + slot * TOPK_C + p;
            g_cand_v[o] = sm->topv[i];
            g_cand_i[o] = sm->topi[i];
        }
        __syncthreads();
        u = send;
    }
}

// ---------------- refine: merge 64 coarse -> top16, exact fp32 -> top-8 ----
__global__ __launch_bounds__(256)
void refine_kernel(const float* __restrict__ emb, const float* __restrict__ rules) {
    __shared__ float sims[8][TOPK_C];
    __shared__ int   midx[8][TOPK_C];
    const int w = threadIdx.x >> 5, lane = threadIdx.x & 31;
    const int row = blockIdx.x * 8 + w;

    // merge 64 coarse candidates down to top-16 by coarse value
    float v0 = g_cand_v[(size_t)row * NCANDT + lane];
    float v1 = g_cand_v[(size_t)row * NCANDT + 32 + lane];
    int   i0 = g_cand_i[(size_t)row * NCANDT + lane];
    int   i1 = g_cand_i[(size_t)row * NCANDT + 32 + lane];
    #pragma unroll
    for (int p = 0; p < TOPK_C; ++p) {
        float m = fmaxf(v0, v1);
        #pragma unroll
        for (int o = 16; o; o >>= 1) m = fmaxf(m, __shfl_xor_sync(0xffffffffu, m, o));
        unsigned msk = __ballot_sync(0xffffffffu, v0 == m || v1 == m);
        int wl = __ffs(msk) - 1;
        if (lane == wl) {
            if (v0 == m) { midx[w][p] = i0; v0 = -FLT_MAX; }
            else         { midx[w][p] = i1; v1 = -FLT_MAX; }
        }
    }
    __syncwarp();

    const float* e = emb + (size_t)row * D_DIM;
    float er[12];
    #pragma unroll
    for (int i = 0; i < 12; ++i) er[i] = e[lane + 32 * i];
    const float qi = g_qinv[row];

    #pragma unroll 2
    for (int cnd = 0; cnd < TOPK_C; ++cnd) {
        int idx = midx[w][cnd];
        const float* rr = rules + (size_t)idx * D_DIM;
        float acc = 0.0f;
        #pragma unroll
        for (int i = 0; i < 12; ++i) acc += er[i] * rr[lane + 32 * i];
        #pragma unroll
        for (int o = 16; o; o >>= 1) acc += __shfl_xor_sync(0xffffffffu, acc, o);
        if (lane == 0) sims[w][cnd] = acc * qi * g_rinv[idx];
    }
    __syncwarp();

    if (lane == 0) {
        float s[TOPK_C];
        #pragma unroll
        for (int q = 0; q < TOPK_C; ++q) s[q] = sims[w][q];
        float v[TOPK]; int id8[TOPK];
        #pragma unroll
        for (int p = 0; p < TOPK; ++p) {
            float bm = -FLT_MAX; int bq = 0;
            #pragma unroll
            for (int q = 0; q < TOPK_C; ++q)
                if (s[q] > bm) { bm = s[q]; bq = q; }
            v[p] = bm;
            id8[p] = midx[w][bq];
            s[bq] = -FLT_MAX;
        }
        float m = v[0];
        float ssum = 0.0f;
        float ex[TOPK];
        #pragma unroll
        for (int p = 0; p < TOPK; ++p) { ex[p] = expf(v[p] - m); ssum += ex[p]; }
        float inv = 1.0f / ssum;
        #pragma unroll
        for (int p = 0; p < TOPK; ++p) {
            g_w8f[(size_t)row * TOPK + p] = ex[p] * inv;
            g_i8f[(size_t)row * TOPK + p] = id8[p];
        }
    }
}

// ---------------- epilogue: gather -> gelu(Wx+b) -> LN ---------------------
#define ER 16
__global__ __launch_bounds__(256)
void epilogue_kernel(const float* __restrict__ s0,
                     const float* __restrict__ rules_raw,
                     const float* __restrict__ W,
                     const float* __restrict__ bvec,
                     const float* __restrict__ alpha_p,
                     const float* __restrict__ gamma,
                     const float* __restrict__ beta,
                     float* __restrict__ out) {
    __shared__ float ctx[ER][D_DIM];
    __shared__ float xs[ER][H_DIM];
    __shared__ float w8[ER][TOPK];
    __shared__ int   i8[ER][TOPK];
    __shared__ float mu_s[ER], rs_s[ER];

    const int tid = threadIdx.x;  // 256
    const int r0  = blockIdx.x * ER;

    for (int e = tid; e < ER * TOPK; e += 256) {
        int r = e >> 3, p = e & 7;
        w8[r][p] = g_w8f[(size_t)(r0 + r) * TOPK + p];
        i8[r][p] = g_i8f[(size_t)(r0 + r) * TOPK + p];
    }
    __syncthreads();

    for (int e = tid; e < ER * D_DIM; e += 256) {
        int r = e / D_DIM, d = e - r * D_DIM;
        float acc = 0.0f;
        #pragma unroll
        for (int k = 0; k < TOPK; ++k) {
            int idx = i8[r][k];
            acc += w8[r][k] * rules_raw[(size_t)idx * D_DIM + d] * g_rinv[idx];
        }
        ctx[r][d] = acc;
    }
    __syncthreads();

    const float alpha = *alpha_p;
    const int h = tid;
    float acc[ER];
    #pragma unroll
    for (int r = 0; r < ER; ++r) acc[r] = 0.0f;

    const float4* wr = reinterpret_cast<const float4*>(W + (size_t)h * D_DIM);
    #pragma unroll 4
    for (int dq = 0; dq < D_DIM / 4; ++dq) {
        float4 w4 = wr[dq];
        #pragma unroll
        for (int r = 0; r < ER; ++r) {
            float4 c4 = *reinterpret_cast<const float4*>(&ctx[r][dq * 4]);
            acc[r] += w4.x * c4.x + w4.y * c4.y + w4.z * c4.z + w4.w * c4.w;
        }
    }
    const float bb = bvec[h];
    #pragma unroll
    for (int r = 0; r < ER; ++r) {
        float z = acc[r] + bb;
        float g = 0.5f * z * (1.0f + erff(z * 0.70710678118654752f));
        xs[r][h] = s0[(size_t)(r0 + r) * H_DIM + h] + alpha * g;
    }
    __syncthreads();

    const int w = tid >> 5, lane = tid & 31;
    for (int rr = w; rr < ER; rr += 8) {
        float s = 0.0f, s2 = 0.0f;
        #pragma unroll
        for (int q = 0; q < 8; ++q) {
            float x = xs[rr][lane + 32 * q];
            s += x; s2 += x * x;
        }
        for (int o = 16; o; o >>= 1) {
            s  += __shfl_xor_sync(0xffffffffu, s, o);
            s2 += __shfl_xor_sync(0xffffffffu, s2, o);
        }
        if (lane == 0) {
            float mu  = s * (1.0f / 256.0f);
            float var = s2 * (1.0f / 256.0f) - mu * mu;
            mu_s[rr] = mu;
            rs_s[rr] = rsqrtf(var + 1e-5f);
        }
    }
    __syncthreads();

    const float gm = gamma[h], bt = beta[h];
    #pragma unroll
    for (int r = 0; r < ER; ++r)
        out[(size_t)(r0 + r) * H_DIM + h] = (xs[r][h] - mu_s[r]) * rs_s[r] * gm + bt;
}

// ---------------- launch ----------------------------------------------------
extern "C" void kernel_launch(void* const* d_in, const int* in_sizes, int n_in,
                              void* d_out, int out_size) {
    const float* embeddings = (const float*)d_in[0];
    const float* s0         = (const float*)d_in[1];
    const float* rules      = (const float*)d_in[2];
    const float* W          = (const float*)d_in[3];
    const float* b          = (const float*)d_in[4];
    const float* alpha      = (const float*)d_in[5];
    const float* gamma      = (const float*)d_in[6];
    const float* beta       = (const float*)d_in[7];
    float* out = (float*)d_out;
    (void)in_sizes; (void)n_in; (void)out_size;

    cudaFuncSetAttribute(sims_topk_kernel,
                         cudaFuncAttributeMaxDynamicSharedMemorySize,
                         (int)sizeof(SimsSmem));

    prep_rules_kernel<<<N_PAD, 128>>>(rules);
    prep_q_kernel<<<B_ROWS, 128>>>(embeddings);
    sims_topk_kernel<<<NCTAS, NTHREADS, sizeof(SimsSmem)>>>();
    refine_kernel<<<B_ROWS / 8, 256>>>(embeddings, rules);
    epilogue_kernel<<<B_ROWS / ER, 256>>>(s0, rules, W, b, alpha, gamma, beta, out);
}

// round 9
// speedup vs baseline: 1.7123x; 1.2888x over previous
#include <cuda_runtime.h>
#include <cuda_bf16.h>
#include <math.h>
#include <stdint.h>
#include <float.h>

#define N_RULES 50000
#define N_PAD   50176            // 392 * 128
#define NHALF   25088            // rules per CTA-half
#define TILES   196              // NHALF / 128
#define D_DIM   384
#define B_ROWS  8192
#define H_DIM   256
#define TOPK    8
#define TOPK_C  16               // coarse candidates per half
#define NCAND   32               // 2 halves * 16

#define BM 128
#define BN 128
#define BK 128                   // elems per K-chunk
#define KCH 3                    // 384 / 128
#define TOT (TILES * KCH)        // 588
#define ASTRIDE 392              // elems: 384 + 8  (784B row, LDSM conflict-free)
#define BSTRIDE 136              // elems: 128 + 8  (272B row, LDSM conflict-free)
#define NTHREADS 512

// ---------------- device scratch ----------------
__device__ __nv_bfloat16 g_rb[(size_t)N_PAD * D_DIM];
__device__ float  g_rinv[N_PAD];
__device__ __nv_bfloat16 g_qb[(size_t)B_ROWS * D_DIM];
__device__ float  g_qinv[B_ROWS];
__device__ int    g_topi[(size_t)B_ROWS * NCAND];
__device__ float  g_w8f[(size_t)B_ROWS * TOPK];
__device__ int    g_i8f[(size_t)B_ROWS * TOPK];

// ---------------- smem struct ----------------
struct __align__(16) SimsSmem {
    __nv_bfloat16 As[BM * ASTRIDE];     // 100352 B
    __nv_bfloat16 Bs[3][BN * BSTRIDE];  // 104448 B
    float topv[BM * TOPK_C];            // 8192 B
    int   topi[BM * TOPK_C];            // 8192 B
    float thr[BM];                      // 512 B
    int   lck[BM];                      // 512 B
};                                      // 222208 B

// ---------------- PTX helpers ----------------
__device__ __forceinline__ uint32_t smem_u32(const void* p) {
    uint32_t a;
    asm("{ .reg .u64 t; cvta.to.shared.u64 t, %1; cvt.u32.u64 %0, t; }" : "=r"(a) : "l"(p));
    return a;
}
__device__ __forceinline__ void cp16(uint32_t dst, const void* src) {
    asm volatile("cp.async.cg.shared.global [%0], [%1], 16;" :: "r"(dst), "l"(src));
}
__device__ __forceinline__ void ldsm_x4(uint32_t* r, uint32_t addr) {
    asm volatile("ldmatrix.sync.aligned.m8n8.x4.shared.b16 {%0,%1,%2,%3}, [%4];"
                 : "=r"(r[0]), "=r"(r[1]), "=r"(r[2]), "=r"(r[3]) : "r"(addr));
}
__device__ __forceinline__ void mma16816(float* c, const uint32_t* a,
                                         uint32_t b0, uint32_t b1) {
    asm volatile(
        "mma.sync.aligned.m16n8k16.row.col.f32.bf16.bf16.f32 "
        "{%0,%1,%2,%3}, {%4,%5,%6,%7}, {%8,%9}, {%0,%1,%2,%3};\n"
        : "+f"(c[0]), "+f"(c[1]), "+f"(c[2]), "+f"(c[3])
        : "r"(a[0]), "r"(a[1]), "r"(a[2]), "r"(a[3]), "r"(b0), "r"(b1));
}

// ---------------- prep kernels: normalize + bf16 cast -----------------------
__global__ void prep_rules_kernel(const float* __restrict__ src) {
    int row = blockIdx.x;
    int tid = threadIdx.x;  // 128
    if (row >= N_RULES) {
        for (int d = tid; d < D_DIM; d += 128)
            g_rb[(size_t)row * D_DIM + d] = __float2bfloat16(0.0f);
        if (tid == 0) g_rinv[row] = 0.0f;
        return;
    }
    const float* x = src + (size_t)row * D_DIM;
    float s = 0.0f;
    for (int d = tid; d < D_DIM; d += 128) { float v = x[d]; s += v * v; }
    __shared__ float red[4];
    for (int o = 16; o; o >>= 1) s += __shfl_xor_sync(0xffffffffu, s, o);
    if ((tid & 31) == 0) red[tid >> 5] = s;
    __syncthreads();
    if (tid == 0) {
        float t = red[0] + red[1] + red[2] + red[3];
        red[0] = 1.0f / fmaxf(sqrtf(t), 1e-12f);
    }
    __syncthreads();
    float inv = red[0];
    for (int d = tid; d < D_DIM; d += 128)
        g_rb[(size_t)row * D_DIM + d] = __float2bfloat16(x[d] * inv);
    if (tid == 0) g_rinv[row] = inv;
}

__global__ void prep_q_kernel(const float* __restrict__ src) {
    int row = blockIdx.x;
    int tid = threadIdx.x;  // 128
    const float* x = src + (size_t)row * D_DIM;
    float s = 0.0f;
    for (int d = tid; d < D_DIM; d += 128) { float v = x[d]; s += v * v; }
    __shared__ float red[4];
    for (int o = 16; o; o >>= 1) s += __shfl_xor_sync(0xffffffffu, s, o);
    if ((tid & 31) == 0) red[tid >> 5] = s;
    __syncthreads();
    if (tid == 0) {
        float t = red[0] + red[1] + red[2] + red[3];
        red[0] = 1.0f / fmaxf(sqrtf(t), 1e-12f);
    }
    __syncthreads();
    float inv = red[0];
    for (int d = tid; d < D_DIM; d += 128)
        g_qb[(size_t)row * D_DIM + d] = __float2bfloat16(x[d] * inv);
    if (tid == 0) g_qinv[row] = inv;
}

// ---------------- fused bf16 sims GEMM + streaming coarse top-16 -----------
__device__ __forceinline__ void issue_b_chunk(uint32_t sbB, int tid, int ch, int rule0) {
    int t  = ch / KCH;
    int kc = ch - t * KCH;
    const __nv_bfloat16* src = g_rb + ((size_t)rule0 + (size_t)t * BN) * D_DIM + kc * BK;
    uint32_t bbase = sbB + (uint32_t)(ch % 3) * (BN * BSTRIDE * 2);
    #pragma unroll
    for (int i = 0; i < 4; ++i) {   // 128 rows * 16 uint4 = 2048 / 512 thr
        int e = tid + i * NTHREADS;
        int r = e >> 4;
        int u = e & 15;
        cp16(bbase + (uint32_t)(r * BSTRIDE + u * 8) * 2, src + (size_t)r * D_DIM + u * 8);
    }
    asm volatile("cp.async.commit_group;" ::: "memory");
}

__device__ void topk_insert(SimsSmem* sm, int r, float v, int j) {
    bool done = false;
    while (!done) {
        if (atomicCAS(&sm->lck[r], 0, 1) == 0) {
            volatile float* tv = sm->topv + r * TOPK_C;
            volatile int*   ti = sm->topi + r * TOPK_C;
            float mn = tv[0]; int mp = 0;
            #pragma unroll
            for (int p = 1; p < TOPK_C; ++p) { float x = tv[p]; if (x < mn) { mn = x; mp = p; } }
            if (v > mn) {
                tv[mp] = v;
                ti[mp] = j;
                float nm = v;
                #pragma unroll
                for (int p = 0; p < TOPK_C; ++p) { float x = tv[p]; if (x < nm) nm = x; }
                sm->thr[r] = nm;
            }
            __threadfence_block();
            atomicExch(&sm->lck[r], 0);
            done = true;
        }
    }
}

__global__ __launch_bounds__(NTHREADS, 1)
void sims_topk_kernel() {
    extern __shared__ char smraw[];
    SimsSmem* sm = reinterpret_cast<SimsSmem*>(smraw);
    const uint32_t sbA = smem_u32(sm->As);
    const uint32_t sbB = smem_u32(sm->Bs);

    const int tid    = threadIdx.x;
    const int lane   = tid & 31;
    const int wid    = tid >> 5;            // 0..15
    const int wm     = (wid & 3) * 32;      // 4 m-warps over 128 rows
    const int wn     = (wid >> 2) * 32;     // 4 n-warps over 128 cols
    const int grp    = blockIdx.x >> 1;
    const int half   = blockIdx.x & 1;
    const int row0   = grp * BM;
    const int rule0  = half * NHALF;

    // init top-k state
    for (int i = tid; i < BM * TOPK_C; i += NTHREADS) { sm->topv[i] = -FLT_MAX; sm->topi[i] = 0; }
    for (int i = tid; i < BM; i += NTHREADS)          { sm->thr[i]  = -FLT_MAX; sm->lck[i]  = 0; }

    // resident A: 128 rows x 384 bf16
    {
        const uint4* gq = reinterpret_cast<const uint4*>(g_qb + (size_t)row0 * D_DIM);
        for (int i = tid; i < BM * 48; i += NTHREADS) {
            int r = i / 48, u = i - (i / 48) * 48;
            *reinterpret_cast<uint4*>(
                reinterpret_cast<char*>(sm->As) + (size_t)r * (ASTRIDE * 2) + u * 16) =
                gq[(size_t)r * 48 + u];
        }
    }

    issue_b_chunk(sbB, tid, 0, rule0);
    issue_b_chunk(sbB, tid, 1, rule0);

    // ldmatrix lane addressing (element units)
    const int a_row = (lane & 15);
    const int a_kof = (lane >> 4) << 3;
    const int b_row = ((lane >> 4) << 3) + (lane & 7);
    const int b_kof = ((lane >> 3) & 1) << 3;

    volatile float* vthr = sm->thr;
    float c[2][4][4];

    int t = 0, kc = 0;
    for (int ch = 0; ch < TOT; ++ch) {
        if (kc == 0) {
            #pragma unroll
            for (int mi = 0; mi < 2; ++mi)
                #pragma unroll
                for (int nq = 0; nq < 4; ++nq)
                    #pragma unroll
                    for (int e = 0; e < 4; ++e) c[mi][nq][e] = 0.0f;
        }

        if (ch == TOT - 1)
            asm volatile("cp.async.wait_group 0;" ::: "memory");
        else
            asm volatile("cp.async.wait_group 1;" ::: "memory");
        __syncthreads();

        if (ch + 2 < TOT) issue_b_chunk(sbB, tid, ch + 2, rule0);

        const uint32_t bB = sbB + (uint32_t)(ch % 3) * (BN * BSTRIDE * 2);
        const int k0 = kc * BK;

        #pragma unroll
        for (int ks = 0; ks < 8; ++ks) {
            const int k = k0 + ks * 16;
            uint32_t a[2][4];
            #pragma unroll
            for (int mi = 0; mi < 2; ++mi)
                ldsm_x4(a[mi], sbA + (uint32_t)((wm + mi * 16 + a_row) * ASTRIDE + k + a_kof) * 2);
            uint32_t b[2][4];
            #pragma unroll
            for (int nt = 0; nt < 2; ++nt)
                ldsm_x4(b[nt], bB + (uint32_t)((wn + nt * 16 + b_row) * BSTRIDE + ks * 16 + b_kof) * 2);
            #pragma unroll
            for (int mi = 0; mi < 2; ++mi)
                #pragma unroll
                for (int nq = 0; nq < 4; ++nq)
                    mma16816(c[mi][nq], a[mi],
                             b[nq >> 1][(nq & 1) * 2], b[nq >> 1][(nq & 1) * 2 + 1]);
        }

        if (kc == KCH - 1) {
            const int jb = rule0 + t * BN;
            #pragma unroll
            for (int mi = 0; mi < 2; ++mi) {
                #pragma unroll
                for (int h = 0; h < 2; ++h) {
                    const int r = wm + mi * 16 + (lane >> 2) + h * 8;
                    float cthr = vthr[r];   // monotone: stale => only extra inserts
                    #pragma unroll
                    for (int nq = 0; nq < 4; ++nq) {
                        #pragma unroll
                        for (int e = 0; e < 2; ++e) {
                            float v = c[mi][nq][h * 2 + e];
                            int j = jb + wn + nq * 8 + (lane & 3) * 2 + e;
                            if (v > cthr && j < N_RULES) {
                                topk_insert(sm, r, v, j);
                                cthr = vthr[r];
                            }
                        }
                    }
                }
            }
        }

        if (++kc == KCH) { kc = 0; ++t; }
    }
    __syncthreads();

    // write per-row candidate indices (this half's top-16)
    for (int i = tid; i < BM * TOPK_C; i += NTHREADS) {
        int r = i >> 4, p = i & 15;
        g_topi[(size_t)(row0 + r) * NCAND + half * TOPK_C + p] = sm->topi[i];
    }
}

// ---------------- refine: exact fp32 sims on 32 candidates -> top-8 --------
__global__ __launch_bounds__(256)
void refine_kernel(const float* __restrict__ emb, const float* __restrict__ rules) {
    __shared__ float sims[8][NCAND];
    const int w = threadIdx.x >> 5, lane = threadIdx.x & 31;
    const int row = blockIdx.x * 8 + w;

    const float* e = emb + (size_t)row * D_DIM;
    float er[12];
    #pragma unroll
    for (int i = 0; i < 12; ++i) er[i] = e[lane + 32 * i];
    const float qi = g_qinv[row];

    for (int cnd = 0; cnd < NCAND; ++cnd) {
        int idx = g_topi[(size_t)row * NCAND + cnd];
        const float* rr = rules + (size_t)idx * D_DIM;
        float acc = 0.0f;
        #pragma unroll
        for (int i = 0; i < 12; ++i) acc += er[i] * rr[lane + 32 * i];
        for (int o = 16; o; o >>= 1) acc += __shfl_xor_sync(0xffffffffu, acc, o);
        if (lane == 0) sims[w][cnd] = acc * qi * g_rinv[idx];
    }
    __syncwarp();

    if (lane == 0) {
        float s[NCAND];
        #pragma unroll
        for (int q = 0; q < NCAND; ++q) s[q] = sims[w][q];
        float v[TOPK]; int id8[TOPK];
        #pragma unroll
        for (int p = 0; p < TOPK; ++p) {
            float bm = -FLT_MAX; int bq = 0;
            #pragma unroll
            for (int q = 0; q < NCAND; ++q)
                if (s[q] > bm) { bm = s[q]; bq = q; }
            v[p] = bm;
            id8[p] = g_topi[(size_t)row * NCAND + bq];
            s[bq] = -FLT_MAX;
        }
        float m = v[0];
        float ssum = 0.0f;
        float ex[TOPK];
        #pragma unroll
        for (int p = 0; p < TOPK; ++p) { ex[p] = expf(v[p] - m); ssum += ex[p]; }
        float inv = 1.0f / ssum;
        #pragma unroll
        for (int p = 0; p < TOPK; ++p) {
            g_w8f[(size_t)row * TOPK + p] = ex[p] * inv;
            g_i8f[(size_t)row * TOPK + p] = id8[p];
        }
    }
}

// ---------------- epilogue: gather -> gelu(Wx+b) -> LN ---------------------
#define ER 16
__global__ __launch_bounds__(256)
void epilogue_kernel(const float* __restrict__ s0,
                     const float* __restrict__ rules_raw,
                     const float* __restrict__ W,
                     const float* __restrict__ bvec,
                     const float* __restrict__ alpha_p,
                     const float* __restrict__ gamma,
                     const float* __restrict__ beta,
                     float* __restrict__ out) {
    __shared__ float ctx[ER][D_DIM];
    __shared__ float xs[ER][H_DIM];
    __shared__ float w8[ER][TOPK];
    __shared__ int   i8[ER][TOPK];
    __shared__ float mu_s[ER], rs_s[ER];

    const int tid = threadIdx.x;  // 256
    const int r0  = blockIdx.x * ER;

    for (int e = tid; e < ER * TOPK; e += 256) {
        int r = e >> 3, p = e & 7;
        w8[r][p] = g_w8f[(size_t)(r0 + r) * TOPK + p];
        i8[r][p] = g_i8f[(size_t)(r0 + r) * TOPK + p];
    }
    __syncthreads();

    for (int e = tid; e < ER * D_DIM; e += 256) {
        int r = e / D_DIM, d = e - r * D_DIM;
        float acc = 0.0f;
        #pragma unroll
        for (int k = 0; k < TOPK; ++k) {
            int idx = i8[r][k];
            acc += w8[r][k] * rules_raw[(size_t)idx * D_DIM + d] * g_rinv[idx];
        }
        ctx[r][d] = acc;
    }
    __syncthreads();

    const float alpha = *alpha_p;
    const int h = tid;
    float acc[ER];
    #pragma unroll
    for (int r = 0; r < ER; ++r) acc[r] = 0.0f;

    const float4* wr = reinterpret_cast<const float4*>(W + (size_t)h * D_DIM);
    #pragma unroll 4
    for (int dq = 0; dq < D_DIM / 4; ++dq) {
        float4 w4 = wr[dq];
        #pragma unroll
        for (int r = 0; r < ER; ++r) {
            float4 c4 = *reinterpret_cast<const float4*>(&ctx[r][dq * 4]);
            acc[r] += w4.x * c4.x + w4.y * c4.y + w4.z * c4.z + w4.w * c4.w;
        }
    }
    const float bb = bvec[h];
    #pragma unroll
    for (int r = 0; r < ER; ++r) {
        float z = acc[r] + bb;
        float g = 0.5f * z * (1.0f + erff(z * 0.70710678118654752f));
        xs[r][h] = s0[(size_t)(r0 + r) * H_DIM + h] + alpha * g;
    }
    __syncthreads();

    const int w = tid >> 5, lane = tid & 31;
    for (int rr = w; rr < ER; rr += 8) {
        float s = 0.0f, s2 = 0.0f;
        #pragma unroll
        for (int q = 0; q < 8; ++q) {
            float x = xs[rr][lane + 32 * q];
            s += x; s2 += x * x;
        }
        for (int o = 16; o; o >>= 1) {
            s  += __shfl_xor_sync(0xffffffffu, s, o);
            s2 += __shfl_xor_sync(0xffffffffu, s2, o);
        }
        if (lane == 0) {
            float mu  = s * (1.0f / 256.0f);
            float var = s2 * (1.0f / 256.0f) - mu * mu;
            mu_s[rr] = mu;
            rs_s[rr] = rsqrtf(var + 1e-5f);
        }
    }
    __syncthreads();

    const float gm = gamma[h], bt = beta[h];
    #pragma unroll
    for (int r = 0; r < ER; ++r)
        out[(size_t)(r0 + r) * H_DIM + h] = (xs[r][h] - mu_s[r]) * rs_s[r] * gm + bt;
}

// ---------------- launch ----------------------------------------------------
extern "C" void kernel_launch(void* const* d_in, const int* in_sizes, int n_in,
                              void* d_out, int out_size) {
    const float* embeddings = (const float*)d_in[0];
    const float* s0         = (const float*)d_in[1];
    const float* rules      = (const float*)d_in[2];
    const float* W          = (const float*)d_in[3];
    const float* b          = (const float*)d_in[4];
    const float* alpha      = (const float*)d_in[5];
    const float* gamma      = (const float*)d_in[6];
    const float* beta       = (const float*)d_in[7];
    float* out = (float*)d_out;
    (void)in_sizes; (void)n_in; (void)out_size;

    cudaFuncSetAttribute(sims_topk_kernel,
                         cudaFuncAttributeMaxDynamicSharedMemorySize,
                         (int)sizeof(SimsSmem));

    prep_rules_kernel<<<N_PAD, 128>>>(rules);
    prep_q_kernel<<<B_ROWS, 128>>>(embeddings);
    sims_topk_kernel<<<128, NTHREADS, sizeof(SimsSmem)>>>();
    refine_kernel<<<B_ROWS / 8, 256>>>(embeddings, rules);
    epilogue_kernel<<<B_ROWS / ER, 256>>>(s0, rules, W, b, alpha, gamma, beta, out);
}